// round 14
// baseline (speedup 1.0000x reference)
#include <cuda_runtime.h>
#include <mma.h>
#include <cstdint>

using namespace nvcuda;

#define N_NODES 100000
#define N_EDGES 1600000
#define IN_DIM  128
#define HID_DIM 64
#define OUT_DIM 32
#define MAXD    64        // P(Poisson(16) > 64) ~ 1e-18: safe padded degree

// ---- device scratch (static globals: no runtime allocation allowed) ----
__device__ int   g_fill[N_NODES];             // becomes degree after scatter
__device__ int   g_slot[N_NODES * MAXD];      // padded adjacency (by dst)
__device__ float g_dinv[N_NODES];
__device__ float g_h1[N_NODES * HID_DIM];     // x @ W1
__device__ float g_a1[N_NODES * HID_DIM];     // relu(agg(h1) + b1)
__device__ float g_h2[N_NODES * OUT_DIM];     // a1 @ W2

__device__ __forceinline__ float* buf_sel(int sel) {
    switch (sel) {
        case 0: return g_h1;
        case 1: return g_a1;
        default: return g_h2;
    }
}

// ---- f32x2 packed helpers (exact IEEE fp32 lanes) ----
__device__ __forceinline__ unsigned long long ffma2(
    unsigned long long a, unsigned long long b, unsigned long long c) {
    unsigned long long d;
    asm("fma.rn.f32x2 %0, %1, %2, %3;" : "=l"(d) : "l"(a), "l"(b), "l"(c));
    return d;
}
__device__ __forceinline__ unsigned long long pack2(float x) {
    unsigned long long d;
    asm("mov.b64 %0, {%1, %1};" : "=l"(d) : "f"(x));
    return d;
}
__device__ __forceinline__ void lds128_u64x2(
    unsigned long long& a, unsigned long long& b, uint32_t saddr) {
    asm volatile("ld.shared.v2.u64 {%0, %1}, [%2];"
                 : "=l"(a), "=l"(b) : "r"(saddr));
}

// ---------------------------------------------------------------- CSR build
__global__ void zero_fill_kernel() {
    int i = blockIdx.x * blockDim.x + threadIdx.x;
    if (i * 4 < N_NODES) {
        int4 z = {0, 0, 0, 0};
        if (i * 4 + 3 < N_NODES) *(int4*)&g_fill[i * 4] = z;
        else for (int k = i * 4; k < N_NODES; k++) g_fill[k] = 0;
    }
}

__global__ void scatter_kernel(const int* __restrict__ ei) {
    int t = blockIdx.x * blockDim.x + threadIdx.x;
    int e = t * 2;
    if (e + 2 <= N_EDGES) {
        int2 s2 = *(const int2*)&ei[e];
        int2 d2 = *(const int2*)&ei[N_EDGES + e];
        if ((unsigned)s2.x < N_NODES && (unsigned)d2.x < N_NODES) {
            int p = atomicAdd(&g_fill[d2.x], 1);
            if (p < MAXD) g_slot[d2.x * MAXD + p] = s2.x;
        }
        if ((unsigned)s2.y < N_NODES && (unsigned)d2.y < N_NODES) {
            int p = atomicAdd(&g_fill[d2.y], 1);
            if (p < MAXD) g_slot[d2.y * MAXD + p] = s2.y;
        }
    } else if (e < N_EDGES) {
        unsigned src = (unsigned)ei[e];
        unsigned dst = (unsigned)ei[N_EDGES + e];
        if (src < N_NODES && dst < N_NODES) {
            int p = atomicAdd(&g_fill[dst], 1);
            if (p < MAXD) g_slot[dst * MAXD + p] = (int)src;
        }
    }
}

__global__ void dinv_kernel() {
    int i = blockIdx.x * blockDim.x + threadIdx.x;
    if (i < N_NODES) g_dinv[i] = rsqrtf((float)(g_fill[i] + 1));  // +1 self loop
}

// ---------------------------------------------------------------- GEMM1: tf32 wmma
// H[N,64] = X[N,128] @ W[128,64].  Block: 64 rows x 64 cols, 8 warps.
// X staged in SMEM in two k-halves (16 KB); W fully staged (32 KB). 48 KB total.
// Warp w owns output tiles (rt=w/4, ct=w%4) and (rt=w/4+2, ct=w%4) -> shares fb.
__global__ __launch_bounds__(256, 4)
void gemm1_wmma_kernel(const float* __restrict__ X,
                       const float* __restrict__ W) {
    __shared__ float Xs[64 * 64];     // 16 KB (one k-half)
    __shared__ float Ws[IN_DIM * HID_DIM];  // 32 KB

    float* H = g_h1;
    const int tid  = threadIdx.x;
    const int warp = tid >> 5;
    const int row0 = blockIdx.x * 64;

    // stage W (row-major 128x64)
    {
        const float4* W4 = (const float4*)W;
        float4* Ws4 = (float4*)Ws;
        for (int i = tid; i < IN_DIM * HID_DIM / 4; i += 256) Ws4[i] = W4[i];
    }

    const int rt = (warp >> 2);        // 0..1
    const int ct = (warp & 3);         // 0..3

    wmma::fragment<wmma::accumulator, 16, 16, 8, float> acc0, acc1;
    wmma::fill_fragment(acc0, 0.0f);
    wmma::fill_fragment(acc1, 0.0f);

    const float4* X4 = (const float4*)X;

    for (int h = 0; h < 2; h++) {
        // stage X k-half: rows row0..row0+64, cols h*64..h*64+64
        __syncthreads();   // protect Xs reuse across halves
        {
            float4* Xs4 = (float4*)Xs;
            for (int i = tid; i < 64 * 16; i += 256) {
                int r  = i >> 4;            // 0..63
                int c4 = i & 15;            // 0..15
                int row = row0 + r;
                if (row >= N_NODES) row = N_NODES - 1;   // clamp (stores guarded)
                Xs4[r * 16 + c4] = X4[row * (IN_DIM / 4) + h * 16 + c4];
            }
        }
        __syncthreads();

#pragma unroll
        for (int kt = 0; kt < 8; kt++) {
            wmma::fragment<wmma::matrix_a, 16, 16, 8, wmma::precision::tf32,
                           wmma::row_major> fa0, fa1;
            wmma::fragment<wmma::matrix_b, 16, 16, 8, wmma::precision::tf32,
                           wmma::row_major> fb;
            int kglob = h * 64 + kt * 8;
            wmma::load_matrix_sync(fa0, &Xs[(rt * 16) * 64 + kt * 8], 64);
            wmma::load_matrix_sync(fa1, &Xs[((rt + 2) * 16) * 64 + kt * 8], 64);
            wmma::load_matrix_sync(fb, &Ws[kglob * HID_DIM + ct * 16], HID_DIM);
#pragma unroll
            for (int i = 0; i < fa0.num_elements; i++) {
                fa0.x[i] = wmma::__float_to_tf32(fa0.x[i]);
                fa1.x[i] = wmma::__float_to_tf32(fa1.x[i]);
            }
#pragma unroll
            for (int i = 0; i < fb.num_elements; i++)
                fb.x[i] = wmma::__float_to_tf32(fb.x[i]);
            wmma::mma_sync(acc0, fa0, fb, acc0);
            wmma::mma_sync(acc1, fa1, fb, acc1);
        }
    }

    // store (tiles are 16-row aligned; N_NODES % 16 == 0 so tiles are all-in or all-out)
    int r0 = row0 + rt * 16;
    int r1 = row0 + (rt + 2) * 16;
    if (r0 + 16 <= N_NODES)
        wmma::store_matrix_sync(&H[r0 * HID_DIM + ct * 16], acc0, HID_DIM,
                                wmma::mem_row_major);
    if (r1 + 16 <= N_NODES)
        wmma::store_matrix_sync(&H[r1 * HID_DIM + ct * 16], acc1, HID_DIM,
                                wmma::mem_row_major);
}

// ---------------------------------------------------------------- GEMM (f32x2) for layer 2
template <int FIN, int FOUT, int TR, int CPT, int XSEL>
__launch_bounds__(256, 2)
__global__ void gemm_kernel(const float* __restrict__ Xarg,
                            const float* __restrict__ W,
                            int out_sel) {
    constexpr int CG = FOUT / CPT;
    constexpr int RG = 256 / CG;
    constexpr int RB = RG * TR;
    constexpr int C2 = CPT / 2;
    constexpr int C4 = CPT / 4;

    const float* X = (XSEL < 0) ? Xarg : buf_sel(XSEL);
    float* H = buf_sel(out_sel);

    __shared__ float Ws[FIN * FOUT];
    for (int i = threadIdx.x; i < FIN * FOUT; i += 256) Ws[i] = W[i];
    __syncthreads();

    const int cg   = threadIdx.x % CG;
    const int rg   = threadIdx.x / CG;
    const int row0 = blockIdx.x * RB + rg * TR;

    const uint32_t ws_col = (uint32_t)__cvta_generic_to_shared(Ws)
                          + (uint32_t)(cg * CPT * 4);

    unsigned long long acc[TR][C2];
#pragma unroll
    for (int r = 0; r < TR; r++)
#pragma unroll
        for (int c = 0; c < C2; c++) acc[r][c] = 0ull;

    const float4* X4 = (const float4*)X;
    int rowc[TR];
#pragma unroll
    for (int r = 0; r < TR; r++) {
        int row = row0 + r;
        rowc[r] = (row < N_NODES) ? row : (N_NODES - 1);
    }

#pragma unroll 4
    for (int kk = 0; kk < FIN / 4; kk++) {
        float4 xv[TR];
#pragma unroll
        for (int r = 0; r < TR; r++)
            xv[r] = X4[rowc[r] * (FIN / 4) + kk];
#pragma unroll
        for (int k4 = 0; k4 < 4; k4++) {
            unsigned long long wv[C2];
            uint32_t kaddr = ws_col + (uint32_t)((kk * 4 + k4) * FOUT * 4);
#pragma unroll
            for (int c = 0; c < C4; c++)
                lds128_u64x2(wv[c * 2], wv[c * 2 + 1], kaddr + c * 16);
#pragma unroll
            for (int r = 0; r < TR; r++) {
                float xk = (k4 == 0) ? xv[r].x : (k4 == 1) ? xv[r].y
                         : (k4 == 2) ? xv[r].z : xv[r].w;
                unsigned long long xx = pack2(xk);
#pragma unroll
                for (int c = 0; c < C2; c++)
                    acc[r][c] = ffma2(xx, wv[c], acc[r][c]);
            }
        }
    }

#pragma unroll
    for (int r = 0; r < TR; r++) {
        int row = row0 + r;
        if (row < N_NODES) {
            unsigned long long* Hp =
                (unsigned long long*)&H[row * FOUT + cg * CPT];
#pragma unroll
            for (int c = 0; c < C2; c++) Hp[c] = acc[r][c];
        }
    }
}

// ---------------------------------------------------------------- aggregate
template <bool RELU, int HSEL>
__global__ void agg64_kernel(const float* __restrict__ bias,
                             float* __restrict__ Oarg, int out_sel) {
    const float2* H2 = (const float2*)buf_sel(HSEL);
    float2* O2 = (float2*)((out_sel < 0) ? Oarg : buf_sel(out_sel));

    int node = (blockIdx.x * blockDim.x + threadIdx.x) >> 5;
    int lane = threadIdx.x & 31;
    if (node >= N_NODES) return;

    float di = g_dinv[node];
    float2 h = H2[node * 32 + lane];
    float ax = di * di * h.x, ay = di * di * h.y;

    int deg = g_fill[node];
    if (deg > MAXD) deg = MAXD;
    const int* sl = &g_slot[node * MAXD];
    int j = 0;
    for (; j + 4 <= deg; j += 4) {
        int s0 = sl[j], s1 = sl[j + 1], s2 = sl[j + 2], s3 = sl[j + 3];
        float w0 = di * g_dinv[s0], w1 = di * g_dinv[s1];
        float w2 = di * g_dinv[s2], w3 = di * g_dinv[s3];
        float2 v0 = H2[s0 * 32 + lane];
        float2 v1 = H2[s1 * 32 + lane];
        float2 v2 = H2[s2 * 32 + lane];
        float2 v3 = H2[s3 * 32 + lane];
        ax += w0 * v0.x + w1 * v1.x + w2 * v2.x + w3 * v3.x;
        ay += w0 * v0.y + w1 * v1.y + w2 * v2.y + w3 * v3.y;
    }
    for (; j < deg; j++) {
        int s = sl[j];
        float w = di * g_dinv[s];
        float2 v = H2[s * 32 + lane];
        ax += w * v.x; ay += w * v.y;
    }

    float2 bb = ((const float2*)bias)[lane];
    ax += bb.x; ay += bb.y;
    if (RELU) { ax = fmaxf(ax, 0.f); ay = fmaxf(ay, 0.f); }
    float2 o = {ax, ay};
    O2[node * 32 + lane] = o;
}

template <bool RELU, int HSEL>
__global__ void agg32_kernel(const float* __restrict__ bias,
                             float* __restrict__ Oarg, int out_sel) {
    const float* H = buf_sel(HSEL);
    float* O = (out_sel < 0) ? Oarg : buf_sel(out_sel);

    int node = (blockIdx.x * blockDim.x + threadIdx.x) >> 5;
    int lane = threadIdx.x & 31;
    if (node >= N_NODES) return;

    float di = g_dinv[node];
    float acc = di * di * H[node * 32 + lane];

    int deg = g_fill[node];
    if (deg > MAXD) deg = MAXD;
    const int* sl = &g_slot[node * MAXD];
    int j = 0;
    for (; j + 4 <= deg; j += 4) {
        int s0 = sl[j], s1 = sl[j + 1], s2 = sl[j + 2], s3 = sl[j + 3];
        float w0 = di * g_dinv[s0], w1 = di * g_dinv[s1];
        float w2 = di * g_dinv[s2], w3 = di * g_dinv[s3];
        acc += w0 * H[s0 * 32 + lane] + w1 * H[s1 * 32 + lane]
             + w2 * H[s2 * 32 + lane] + w3 * H[s3 * 32 + lane];
    }
    for (; j < deg; j++) {
        int s = sl[j];
        acc += di * g_dinv[s] * H[s * 32 + lane];
    }

    float v = acc + bias[lane];
    if (RELU) v = fmaxf(v, 0.f);
    O[node * 32 + lane] = v;
}

// ---------------------------------------------------------------- launch
extern "C" void kernel_launch(void* const* d_in, const int* in_sizes, int n_in,
                              void* d_out, int out_size) {
    const float* x  = (const float*)d_in[0];
    const int*   ei = (const int*)d_in[1];
    const float* W1 = (const float*)d_in[2];
    const float* b1 = (const float*)d_in[3];
    const float* W2 = (const float*)d_in[4];
    const float* b2 = (const float*)d_in[5];
    float*       out = (float*)d_out;

    static cudaStream_t s_side = nullptr;
    static cudaEvent_t  s_fork = nullptr, s_join = nullptr;
    if (!s_side) {
        if (cudaStreamCreateWithFlags(&s_side, cudaStreamNonBlocking) != cudaSuccess)
            s_side = nullptr;
        cudaEventCreateWithFlags(&s_fork, cudaEventDisableTiming);
        cudaEventCreateWithFlags(&s_join, cudaEventDisableTiming);
    }
    cudaStream_t sc = s_side ? s_side : 0;

    // fork: adjacency build on side stream
    if (s_side) {
        cudaEventRecord(s_fork, 0);
        cudaStreamWaitEvent(sc, s_fork, 0);
    }
    zero_fill_kernel<<<(N_NODES / 4 + 255) / 256, 256, 0, sc>>>();
    scatter_kernel<<<(N_EDGES / 2 + 255) / 256, 256, 0, sc>>>(ei);
    dinv_kernel<<<(N_NODES + 255) / 256, 256, 0, sc>>>();
    if (s_side) cudaEventRecord(s_join, sc);

    // concurrently on main stream: GEMM1 x@W1 -> g_h1 (tf32 tensor cores)
    gemm1_wmma_kernel<<<(N_NODES + 63) / 64, 256>>>(x, W1);

    // join: agg needs adjacency + g_h1
    if (s_side) cudaStreamWaitEvent(0, s_join, 0);

    agg64_kernel<true, 0><<<(N_NODES * 32 + 255) / 256, 256>>>(b1, nullptr, 1);

    gemm_kernel<HID_DIM, OUT_DIM, 4, 16, 1>
        <<<(N_NODES + 511) / 512, 256>>>(nullptr, W2, 2);
    agg32_kernel<false, 2><<<(N_NODES * 32 + 255) / 256, 256>>>(b2, out, -1);
}

// round 15
// speedup vs baseline: 1.0106x; 1.0106x over previous
#include <cuda_runtime.h>
#include <mma.h>
#include <cstdint>

using namespace nvcuda;

#define N_NODES 100000
#define N_EDGES 1600000
#define IN_DIM  128
#define HID_DIM 64
#define OUT_DIM 32
#define MAXD    64        // P(Poisson(16) > 64) ~ 1e-18: safe padded degree

#define G1_GRID  296      // 2 CTAs/SM x 148 SMs
#define G1_TILES ((N_NODES + 63) / 64)   // 1563

// ---- device scratch (static globals: no runtime allocation allowed) ----
__device__ int   g_fill[N_NODES];
__device__ int   g_slot[N_NODES * MAXD];
__device__ float g_dinv[N_NODES];
__device__ float g_h1[N_NODES * HID_DIM];
__device__ float g_a1[N_NODES * HID_DIM];
__device__ float g_h2[N_NODES * OUT_DIM];

__device__ __forceinline__ float* buf_sel(int sel) {
    switch (sel) {
        case 0: return g_h1;
        case 1: return g_a1;
        default: return g_h2;
    }
}

// ---- f32x2 packed helpers ----
__device__ __forceinline__ unsigned long long ffma2(
    unsigned long long a, unsigned long long b, unsigned long long c) {
    unsigned long long d;
    asm("fma.rn.f32x2 %0, %1, %2, %3;" : "=l"(d) : "l"(a), "l"(b), "l"(c));
    return d;
}
__device__ __forceinline__ unsigned long long pack2(float x) {
    unsigned long long d;
    asm("mov.b64 %0, {%1, %1};" : "=l"(d) : "f"(x));
    return d;
}
__device__ __forceinline__ void lds128_u64x2(
    unsigned long long& a, unsigned long long& b, uint32_t saddr) {
    asm volatile("ld.shared.v2.u64 {%0, %1}, [%2];"
                 : "=l"(a), "=l"(b) : "r"(saddr));
}
__device__ __forceinline__ void cp16(uint32_t saddr, const void* gaddr) {
    asm volatile("cp.async.ca.shared.global [%0], [%1], 16;"
                 :: "r"(saddr), "l"(gaddr));
}

// ---------------------------------------------------------------- CSR build
__global__ void zero_fill_kernel() {
    int i = blockIdx.x * blockDim.x + threadIdx.x;
    if (i * 4 < N_NODES) {
        int4 z = {0, 0, 0, 0};
        if (i * 4 + 3 < N_NODES) *(int4*)&g_fill[i * 4] = z;
        else for (int k = i * 4; k < N_NODES; k++) g_fill[k] = 0;
    }
}

__global__ void scatter_kernel(const int* __restrict__ ei) {
    int t = blockIdx.x * blockDim.x + threadIdx.x;
    int e = t * 2;
    if (e + 2 <= N_EDGES) {
        int2 s2 = *(const int2*)&ei[e];
        int2 d2 = *(const int2*)&ei[N_EDGES + e];
        if ((unsigned)s2.x < N_NODES && (unsigned)d2.x < N_NODES) {
            int p = atomicAdd(&g_fill[d2.x], 1);
            if (p < MAXD) g_slot[d2.x * MAXD + p] = s2.x;
        }
        if ((unsigned)s2.y < N_NODES && (unsigned)d2.y < N_NODES) {
            int p = atomicAdd(&g_fill[d2.y], 1);
            if (p < MAXD) g_slot[d2.y * MAXD + p] = s2.y;
        }
    } else if (e < N_EDGES) {
        unsigned src = (unsigned)ei[e];
        unsigned dst = (unsigned)ei[N_EDGES + e];
        if (src < N_NODES && dst < N_NODES) {
            int p = atomicAdd(&g_fill[dst], 1);
            if (p < MAXD) g_slot[dst * MAXD + p] = (int)src;
        }
    }
}

__global__ void dinv_kernel() {
    int i = blockIdx.x * blockDim.x + threadIdx.x;
    if (i < N_NODES) g_dinv[i] = rsqrtf((float)(g_fill[i] + 1));
}

// ---------------------------------------------------------------- GEMM1: pipelined tf32 wmma
// H[N,64] = X[N,128] @ W[128,64]. 296 persistent-ish CTAs; each loops over
// 64-row tiles. W staged once per CTA. X tiles double-buffered via cp.async
// so DRAM latency overlaps mma compute.
// dynamic smem: Ws[128*64] + Xs[2][64*128] = 96 KB.
__global__ __launch_bounds__(256, 2)
void gemm1_pipe_kernel(const float* __restrict__ X,
                       const float* __restrict__ W) {
    extern __shared__ float dsm[];
    float* Ws = dsm;                    // 8192 floats
    float* Xs0 = dsm + 8192;            // 8192 floats
    float* Xs1 = dsm + 16384;           // 8192 floats

    float* H = g_h1;
    const int tid  = threadIdx.x;
    const int warp = tid >> 5;
    const int rt = warp >> 2;           // 0..1
    const int ct = warp & 3;            // 0..3

    // stage W once (row-major 128x64)
    {
        const float4* W4 = (const float4*)W;
        float4* Ws4 = (float4*)Ws;
        for (int i = tid; i < IN_DIM * HID_DIM / 4; i += 256) Ws4[i] = W4[i];
    }

    const float4* X4 = (const float4*)X;
    const uint32_t xs_addr[2] = {
        (uint32_t)__cvta_generic_to_shared(Xs0),
        (uint32_t)__cvta_generic_to_shared(Xs1)
    };
    float* const xs_ptr[2] = {Xs0, Xs1};

    // stage helper: tile t -> buffer b (32 KB, 8 cp.async x 16B per thread)
    auto stage = [&](int b, int t) {
        int row0 = t * 64;
        uint32_t sb = xs_addr[b];
#pragma unroll
        for (int k = 0; k < 8; k++) {
            int l = tid + k * 256;          // 0..2047
            int r = l >> 5, c4 = l & 31;
            int row = row0 + r;
            if (row >= N_NODES) row = N_NODES - 1;
            cp16(sb + (uint32_t)l * 16, &X4[row * 32 + c4]);
        }
        asm volatile("cp.async.commit_group;");
    };

    int t0 = blockIdx.x;
    if (t0 < G1_TILES) stage(0, t0);
    __syncthreads();   // Ws ready (and first stage committed)

    int cur = 0;
    for (int t = t0; t < G1_TILES; t += G1_GRID) {
        int tn = t + G1_GRID;
        bool has_next = (tn < G1_TILES);
        if (has_next) stage(1 - cur, tn);

        if (has_next) asm volatile("cp.async.wait_group 1;");
        else          asm volatile("cp.async.wait_group 0;");
        __syncthreads();

        const float* Xt = xs_ptr[cur];
        wmma::fragment<wmma::accumulator, 16, 16, 8, float> acc0, acc1;
        wmma::fill_fragment(acc0, 0.0f);
        wmma::fill_fragment(acc1, 0.0f);

#pragma unroll
        for (int kt = 0; kt < 16; kt++) {
            wmma::fragment<wmma::matrix_a, 16, 16, 8, wmma::precision::tf32,
                           wmma::row_major> fa0, fa1;
            wmma::fragment<wmma::matrix_b, 16, 16, 8, wmma::precision::tf32,
                           wmma::row_major> fb;
            wmma::load_matrix_sync(fa0, &Xt[(rt * 16) * 128 + kt * 8], 128);
            wmma::load_matrix_sync(fa1, &Xt[((rt + 2) * 16) * 128 + kt * 8], 128);
            wmma::load_matrix_sync(fb, &Ws[(kt * 8) * HID_DIM + ct * 16], HID_DIM);
#pragma unroll
            for (int i = 0; i < fa0.num_elements; i++) {
                fa0.x[i] = wmma::__float_to_tf32(fa0.x[i]);
                fa1.x[i] = wmma::__float_to_tf32(fa1.x[i]);
            }
#pragma unroll
            for (int i = 0; i < fb.num_elements; i++)
                fb.x[i] = wmma::__float_to_tf32(fb.x[i]);
            wmma::mma_sync(acc0, fa0, fb, acc0);
            wmma::mma_sync(acc1, fa1, fb, acc1);
        }

        int row0 = t * 64;
        int r0 = row0 + rt * 16;
        int r1 = row0 + (rt + 2) * 16;
        if (r0 + 16 <= N_NODES)
            wmma::store_matrix_sync(&H[r0 * HID_DIM + ct * 16], acc0, HID_DIM,
                                    wmma::mem_row_major);
        if (r1 + 16 <= N_NODES)
            wmma::store_matrix_sync(&H[r1 * HID_DIM + ct * 16], acc1, HID_DIM,
                                    wmma::mem_row_major);

        __syncthreads();   // all warps done reading cur before it is restaged
        cur ^= 1;
    }
}

// ---------------------------------------------------------------- GEMM (f32x2) layer 2
template <int FIN, int FOUT, int TR, int CPT, int XSEL>
__launch_bounds__(256, 2)
__global__ void gemm_kernel(const float* __restrict__ Xarg,
                            const float* __restrict__ W,
                            int out_sel) {
    constexpr int CG = FOUT / CPT;
    constexpr int RG = 256 / CG;
    constexpr int RB = RG * TR;
    constexpr int C2 = CPT / 2;
    constexpr int C4 = CPT / 4;

    const float* X = (XSEL < 0) ? Xarg : buf_sel(XSEL);
    float* H = buf_sel(out_sel);

    __shared__ float Ws[FIN * FOUT];
    for (int i = threadIdx.x; i < FIN * FOUT; i += 256) Ws[i] = W[i];
    __syncthreads();

    const int cg   = threadIdx.x % CG;
    const int rg   = threadIdx.x / CG;
    const int row0 = blockIdx.x * RB + rg * TR;

    const uint32_t ws_col = (uint32_t)__cvta_generic_to_shared(Ws)
                          + (uint32_t)(cg * CPT * 4);

    unsigned long long acc[TR][C2];
#pragma unroll
    for (int r = 0; r < TR; r++)
#pragma unroll
        for (int c = 0; c < C2; c++) acc[r][c] = 0ull;

    const float4* X4 = (const float4*)X;
    int rowc[TR];
#pragma unroll
    for (int r = 0; r < TR; r++) {
        int row = row0 + r;
        rowc[r] = (row < N_NODES) ? row : (N_NODES - 1);
    }

#pragma unroll 4
    for (int kk = 0; kk < FIN / 4; kk++) {
        float4 xv[TR];
#pragma unroll
        for (int r = 0; r < TR; r++)
            xv[r] = X4[rowc[r] * (FIN / 4) + kk];
#pragma unroll
        for (int k4 = 0; k4 < 4; k4++) {
            unsigned long long wv[C2];
            uint32_t kaddr = ws_col + (uint32_t)((kk * 4 + k4) * FOUT * 4);
#pragma unroll
            for (int c = 0; c < C4; c++)
                lds128_u64x2(wv[c * 2], wv[c * 2 + 1], kaddr + c * 16);
#pragma unroll
            for (int r = 0; r < TR; r++) {
                float xk = (k4 == 0) ? xv[r].x : (k4 == 1) ? xv[r].y
                         : (k4 == 2) ? xv[r].z : xv[r].w;
                unsigned long long xx = pack2(xk);
#pragma unroll
                for (int c = 0; c < C2; c++)
                    acc[r][c] = ffma2(xx, wv[c], acc[r][c]);
            }
        }
    }

#pragma unroll
    for (int r = 0; r < TR; r++) {
        int row = row0 + r;
        if (row < N_NODES) {
            unsigned long long* Hp =
                (unsigned long long*)&H[row * FOUT + cg * CPT];
#pragma unroll
            for (int c = 0; c < C2; c++) Hp[c] = acc[r][c];
        }
    }
}

// ---------------------------------------------------------------- aggregate
template <bool RELU, int HSEL>
__global__ void agg64_kernel(const float* __restrict__ bias,
                             float* __restrict__ Oarg, int out_sel) {
    const float2* H2 = (const float2*)buf_sel(HSEL);
    float2* O2 = (float2*)((out_sel < 0) ? Oarg : buf_sel(out_sel));

    int node = (blockIdx.x * blockDim.x + threadIdx.x) >> 5;
    int lane = threadIdx.x & 31;
    if (node >= N_NODES) return;

    float di = g_dinv[node];
    float2 h = H2[node * 32 + lane];
    float ax = di * di * h.x, ay = di * di * h.y;

    int deg = g_fill[node];
    if (deg > MAXD) deg = MAXD;
    const int* sl = &g_slot[node * MAXD];
    int j = 0;
    for (; j + 4 <= deg; j += 4) {
        int s0 = sl[j], s1 = sl[j + 1], s2 = sl[j + 2], s3 = sl[j + 3];
        float w0 = di * g_dinv[s0], w1 = di * g_dinv[s1];
        float w2 = di * g_dinv[s2], w3 = di * g_dinv[s3];
        float2 v0 = H2[s0 * 32 + lane];
        float2 v1 = H2[s1 * 32 + lane];
        float2 v2 = H2[s2 * 32 + lane];
        float2 v3 = H2[s3 * 32 + lane];
        ax += w0 * v0.x + w1 * v1.x + w2 * v2.x + w3 * v3.x;
        ay += w0 * v0.y + w1 * v1.y + w2 * v2.y + w3 * v3.y;
    }
    for (; j < deg; j++) {
        int s = sl[j];
        float w = di * g_dinv[s];
        float2 v = H2[s * 32 + lane];
        ax += w * v.x; ay += w * v.y;
    }

    float2 bb = ((const float2*)bias)[lane];
    ax += bb.x; ay += bb.y;
    if (RELU) { ax = fmaxf(ax, 0.f); ay = fmaxf(ay, 0.f); }
    float2 o = {ax, ay};
    O2[node * 32 + lane] = o;
}

template <bool RELU, int HSEL>
__global__ void agg32_kernel(const float* __restrict__ bias,
                             float* __restrict__ Oarg, int out_sel) {
    const float* H = buf_sel(HSEL);
    float* O = (out_sel < 0) ? Oarg : buf_sel(out_sel);

    int node = (blockIdx.x * blockDim.x + threadIdx.x) >> 5;
    int lane = threadIdx.x & 31;
    if (node >= N_NODES) return;

    float di = g_dinv[node];
    float acc = di * di * H[node * 32 + lane];

    int deg = g_fill[node];
    if (deg > MAXD) deg = MAXD;
    const int* sl = &g_slot[node * MAXD];
    int j = 0;
    for (; j + 4 <= deg; j += 4) {
        int s0 = sl[j], s1 = sl[j + 1], s2 = sl[j + 2], s3 = sl[j + 3];
        float w0 = di * g_dinv[s0], w1 = di * g_dinv[s1];
        float w2 = di * g_dinv[s2], w3 = di * g_dinv[s3];
        acc += w0 * H[s0 * 32 + lane] + w1 * H[s1 * 32 + lane]
             + w2 * H[s2 * 32 + lane] + w3 * H[s3 * 32 + lane];
    }
    for (; j < deg; j++) {
        int s = sl[j];
        acc += di * g_dinv[s] * H[s * 32 + lane];
    }

    float v = acc + bias[lane];
    if (RELU) v = fmaxf(v, 0.f);
    O[node * 32 + lane] = v;
}

// ---------------------------------------------------------------- launch
extern "C" void kernel_launch(void* const* d_in, const int* in_sizes, int n_in,
                              void* d_out, int out_size) {
    const float* x  = (const float*)d_in[0];
    const int*   ei = (const int*)d_in[1];
    const float* W1 = (const float*)d_in[2];
    const float* b1 = (const float*)d_in[3];
    const float* W2 = (const float*)d_in[4];
    const float* b2 = (const float*)d_in[5];
    float*       out = (float*)d_out;

    static cudaStream_t s_side = nullptr;
    static cudaEvent_t  s_fork = nullptr, s_join = nullptr;
    static bool attr_done = false;
    if (!attr_done) {
        cudaFuncSetAttribute(gemm1_pipe_kernel,
                             cudaFuncAttributeMaxDynamicSharedMemorySize,
                             98304);
        attr_done = true;
    }
    if (!s_side) {
        if (cudaStreamCreateWithFlags(&s_side, cudaStreamNonBlocking) != cudaSuccess)
            s_side = nullptr;
        cudaEventCreateWithFlags(&s_fork, cudaEventDisableTiming);
        cudaEventCreateWithFlags(&s_join, cudaEventDisableTiming);
    }
    cudaStream_t sc = s_side ? s_side : 0;

    // fork: adjacency build on side stream
    if (s_side) {
        cudaEventRecord(s_fork, 0);
        cudaStreamWaitEvent(sc, s_fork, 0);
    }
    zero_fill_kernel<<<(N_NODES / 4 + 255) / 256, 256, 0, sc>>>();
    scatter_kernel<<<(N_EDGES / 2 + 255) / 256, 256, 0, sc>>>(ei);
    dinv_kernel<<<(N_NODES + 255) / 256, 256, 0, sc>>>();
    if (s_side) cudaEventRecord(s_join, sc);

    // concurrently on main stream: GEMM1 (cp.async pipelined tf32 wmma)
    gemm1_pipe_kernel<<<G1_GRID, 256, 98304>>>(x, W1);

    // join: agg needs adjacency + g_h1
    if (s_side) cudaStreamWaitEvent(0, s_join, 0);

    agg64_kernel<true, 0><<<(N_NODES * 32 + 255) / 256, 256>>>(b1, nullptr, 1);

    gemm_kernel<HID_DIM, OUT_DIM, 4, 16, 1>
        <<<(N_NODES + 511) / 512, 256>>>(nullptr, W2, 2);
    agg32_kernel<false, 2><<<(N_NODES * 32 + 255) / 256, 256>>>(b2, out, -1);
}

// round 16
// speedup vs baseline: 1.1828x; 1.1705x over previous
#include <cuda_runtime.h>
#include <mma.h>
#include <cstdint>

using namespace nvcuda;

#define N_NODES 100000
#define N_EDGES 1600000
#define IN_DIM  128
#define HID_DIM 64
#define OUT_DIM 32
#define MAXD    64        // P(Poisson(16) > 64) ~ 1e-18: safe padded degree

#define G1_GRID  296      // 2 CTAs/SM x 148 SMs
#define G1_TILES ((N_NODES + 63) / 64)   // 1563
#define XLD 132           // padded X tile leading dim (floats): kills LDSM bank conflicts
#define WLD 68            // padded W leading dim (floats)

// ---- device scratch (static globals: no runtime allocation allowed) ----
__device__ int   g_fill[N_NODES];
__device__ int   g_slot[N_NODES * MAXD];
__device__ float g_dinv[N_NODES];
__device__ float g_h1[N_NODES * HID_DIM];
__device__ float g_a1[N_NODES * HID_DIM];
__device__ float g_h2[N_NODES * OUT_DIM];

__device__ __forceinline__ float* buf_sel(int sel) {
    switch (sel) {
        case 0: return g_h1;
        case 1: return g_a1;
        default: return g_h2;
    }
}

// ---- f32x2 packed helpers ----
__device__ __forceinline__ unsigned long long ffma2(
    unsigned long long a, unsigned long long b, unsigned long long c) {
    unsigned long long d;
    asm("fma.rn.f32x2 %0, %1, %2, %3;" : "=l"(d) : "l"(a), "l"(b), "l"(c));
    return d;
}
__device__ __forceinline__ unsigned long long pack2(float x) {
    unsigned long long d;
    asm("mov.b64 %0, {%1, %1};" : "=l"(d) : "f"(x));
    return d;
}
__device__ __forceinline__ void lds128_u64x2(
    unsigned long long& a, unsigned long long& b, uint32_t saddr) {
    asm volatile("ld.shared.v2.u64 {%0, %1}, [%2];"
                 : "=l"(a), "=l"(b) : "r"(saddr));
}
__device__ __forceinline__ void cp16(uint32_t saddr, const void* gaddr) {
    asm volatile("cp.async.ca.shared.global [%0], [%1], 16;"
                 :: "r"(saddr), "l"(gaddr));
}

// ---------------------------------------------------------------- CSR build
__global__ void zero_fill_kernel() {
    int i = blockIdx.x * blockDim.x + threadIdx.x;
    if (i * 4 < N_NODES) {
        int4 z = {0, 0, 0, 0};
        if (i * 4 + 3 < N_NODES) *(int4*)&g_fill[i * 4] = z;
        else for (int k = i * 4; k < N_NODES; k++) g_fill[k] = 0;
    }
}

__global__ void scatter_kernel(const int* __restrict__ ei) {
    int t = blockIdx.x * blockDim.x + threadIdx.x;
    int e = t * 2;
    if (e + 2 <= N_EDGES) {
        int2 s2 = *(const int2*)&ei[e];
        int2 d2 = *(const int2*)&ei[N_EDGES + e];
        if ((unsigned)s2.x < N_NODES && (unsigned)d2.x < N_NODES) {
            int p = atomicAdd(&g_fill[d2.x], 1);
            if (p < MAXD) g_slot[d2.x * MAXD + p] = s2.x;
        }
        if ((unsigned)s2.y < N_NODES && (unsigned)d2.y < N_NODES) {
            int p = atomicAdd(&g_fill[d2.y], 1);
            if (p < MAXD) g_slot[d2.y * MAXD + p] = s2.y;
        }
    } else if (e < N_EDGES) {
        unsigned src = (unsigned)ei[e];
        unsigned dst = (unsigned)ei[N_EDGES + e];
        if (src < N_NODES && dst < N_NODES) {
            int p = atomicAdd(&g_fill[dst], 1);
            if (p < MAXD) g_slot[dst * MAXD + p] = (int)src;
        }
    }
}

__global__ void dinv_kernel() {
    int i = blockIdx.x * blockDim.x + threadIdx.x;
    if (i < N_NODES) g_dinv[i] = rsqrtf((float)(g_fill[i] + 1));
}

// ---------------------------------------------------------------- GEMM1: pipelined tf32 wmma
// H[N,64] = X[N,128] @ W[128,64]. 296 CTAs loop over 64-row tiles.
// W staged once per CTA (padded stride WLD); X double-buffered via cp.async
// (padded stride XLD). Padding breaks the all-rows-same-bank LDSM conflicts
// that pinned every previous variant at ~80% l1tex.
__global__ __launch_bounds__(256, 2)
void gemm1_pipe_kernel(const float* __restrict__ X,
                       const float* __restrict__ W) {
    extern __shared__ float dsm[];
    float* Ws  = dsm;                       // 128*WLD = 8704 floats
    float* Xs0 = dsm + 128 * WLD;           // 64*XLD  = 8448 floats
    float* Xs1 = Xs0 + 64 * XLD;

    float* H = g_h1;
    const int tid  = threadIdx.x;
    const int warp = tid >> 5;
    const int rt = warp >> 2;           // 0..1
    const int ct = warp & 3;            // 0..3

    // stage W once: row-major 128x64 -> padded stride WLD
    {
        const float4* W4 = (const float4*)W;
        for (int i = tid; i < IN_DIM * (HID_DIM / 4); i += 256) {
            int r  = i >> 4;            // 0..127
            int c4 = i & 15;            // 0..15
            *(float4*)&Ws[r * WLD + c4 * 4] = W4[r * 16 + c4];
        }
    }

    const float4* X4 = (const float4*)X;
    const uint32_t xs_addr[2] = {
        (uint32_t)__cvta_generic_to_shared(Xs0),
        (uint32_t)__cvta_generic_to_shared(Xs1)
    };
    float* const xs_ptr[2] = {Xs0, Xs1};

    // stage helper: tile t -> buffer b (64 rows x 128 floats, padded stride)
    auto stage = [&](int b, int t) {
        int row0 = t * 64;
        uint32_t sb = xs_addr[b];
#pragma unroll
        for (int k = 0; k < 8; k++) {
            int l = tid + k * 256;          // 0..2047
            int r = l >> 5, c4 = l & 31;
            int row = row0 + r;
            if (row >= N_NODES) row = N_NODES - 1;
            cp16(sb + (uint32_t)(r * XLD + c4 * 4) * 4, &X4[row * 32 + c4]);
        }
        asm volatile("cp.async.commit_group;");
    };

    int t0 = blockIdx.x;
    if (t0 < G1_TILES) stage(0, t0);
    __syncthreads();   // Ws ready (and first stage committed)

    int cur = 0;
    for (int t = t0; t < G1_TILES; t += G1_GRID) {
        int tn = t + G1_GRID;
        bool has_next = (tn < G1_TILES);
        if (has_next) stage(1 - cur, tn);

        if (has_next) asm volatile("cp.async.wait_group 1;");
        else          asm volatile("cp.async.wait_group 0;");
        __syncthreads();

        const float* Xt = xs_ptr[cur];
        wmma::fragment<wmma::accumulator, 16, 16, 8, float> acc0, acc1;
        wmma::fill_fragment(acc0, 0.0f);
        wmma::fill_fragment(acc1, 0.0f);

#pragma unroll
        for (int kt = 0; kt < 16; kt++) {
            wmma::fragment<wmma::matrix_a, 16, 16, 8, wmma::precision::tf32,
                           wmma::row_major> fa0, fa1;
            wmma::fragment<wmma::matrix_b, 16, 16, 8, wmma::precision::tf32,
                           wmma::row_major> fb;
            wmma::load_matrix_sync(fa0, &Xt[(rt * 16) * XLD + kt * 8], XLD);
            wmma::load_matrix_sync(fa1, &Xt[((rt + 2) * 16) * XLD + kt * 8], XLD);
            wmma::load_matrix_sync(fb, &Ws[(kt * 8) * WLD + ct * 16], WLD);
#pragma unroll
            for (int i = 0; i < fa0.num_elements; i++) {
                fa0.x[i] = wmma::__float_to_tf32(fa0.x[i]);
                fa1.x[i] = wmma::__float_to_tf32(fa1.x[i]);
            }
#pragma unroll
            for (int i = 0; i < fb.num_elements; i++)
                fb.x[i] = wmma::__float_to_tf32(fb.x[i]);
            wmma::mma_sync(acc0, fa0, fb, acc0);
            wmma::mma_sync(acc1, fa1, fb, acc1);
        }

        int row0 = t * 64;
        int r0 = row0 + rt * 16;
        int r1 = row0 + (rt + 2) * 16;
        if (r0 + 16 <= N_NODES)
            wmma::store_matrix_sync(&H[r0 * HID_DIM + ct * 16], acc0, HID_DIM,
                                    wmma::mem_row_major);
        if (r1 + 16 <= N_NODES)
            wmma::store_matrix_sync(&H[r1 * HID_DIM + ct * 16], acc1, HID_DIM,
                                    wmma::mem_row_major);

        __syncthreads();   // all warps done reading cur before restage
        cur ^= 1;
    }
}

#define G1_SMEM ((128 * WLD + 2 * 64 * XLD) * 4)   // 102400 B

// ---------------------------------------------------------------- GEMM (f32x2) layer 2
template <int FIN, int FOUT, int TR, int CPT, int XSEL>
__launch_bounds__(256, 2)
__global__ void gemm_kernel(const float* __restrict__ Xarg,
                            const float* __restrict__ W,
                            int out_sel) {
    constexpr int CG = FOUT / CPT;
    constexpr int RG = 256 / CG;
    constexpr int RB = RG * TR;
    constexpr int C2 = CPT / 2;
    constexpr int C4 = CPT / 4;

    const float* X = (XSEL < 0) ? Xarg : buf_sel(XSEL);
    float* H = buf_sel(out_sel);

    __shared__ float Ws[FIN * FOUT];
    for (int i = threadIdx.x; i < FIN * FOUT; i += 256) Ws[i] = W[i];
    __syncthreads();

    const int cg   = threadIdx.x % CG;
    const int rg   = threadIdx.x / CG;
    const int row0 = blockIdx.x * RB + rg * TR;

    const uint32_t ws_col = (uint32_t)__cvta_generic_to_shared(Ws)
                          + (uint32_t)(cg * CPT * 4);

    unsigned long long acc[TR][C2];
#pragma unroll
    for (int r = 0; r < TR; r++)
#pragma unroll
        for (int c = 0; c < C2; c++) acc[r][c] = 0ull;

    const float4* X4 = (const float4*)X;
    int rowc[TR];
#pragma unroll
    for (int r = 0; r < TR; r++) {
        int row = row0 + r;
        rowc[r] = (row < N_NODES) ? row : (N_NODES - 1);
    }

#pragma unroll 4
    for (int kk = 0; kk < FIN / 4; kk++) {
        float4 xv[TR];
#pragma unroll
        for (int r = 0; r < TR; r++)
            xv[r] = X4[rowc[r] * (FIN / 4) + kk];
#pragma unroll
        for (int k4 = 0; k4 < 4; k4++) {
            unsigned long long wv[C2];
            uint32_t kaddr = ws_col + (uint32_t)((kk * 4 + k4) * FOUT * 4);
#pragma unroll
            for (int c = 0; c < C4; c++)
                lds128_u64x2(wv[c * 2], wv[c * 2 + 1], kaddr + c * 16);
#pragma unroll
            for (int r = 0; r < TR; r++) {
                float xk = (k4 == 0) ? xv[r].x : (k4 == 1) ? xv[r].y
                         : (k4 == 2) ? xv[r].z : xv[r].w;
                unsigned long long xx = pack2(xk);
#pragma unroll
                for (int c = 0; c < C2; c++)
                    acc[r][c] = ffma2(xx, wv[c], acc[r][c]);
            }
        }
    }

#pragma unroll
    for (int r = 0; r < TR; r++) {
        int row = row0 + r;
        if (row < N_NODES) {
            unsigned long long* Hp =
                (unsigned long long*)&H[row * FOUT + cg * CPT];
#pragma unroll
            for (int c = 0; c < C2; c++) Hp[c] = acc[r][c];
        }
    }
}

// ---------------------------------------------------------------- aggregate
template <bool RELU, int HSEL>
__global__ void agg64_kernel(const float* __restrict__ bias,
                             float* __restrict__ Oarg, int out_sel) {
    const float2* H2 = (const float2*)buf_sel(HSEL);
    float2* O2 = (float2*)((out_sel < 0) ? Oarg : buf_sel(out_sel));

    int node = (blockIdx.x * blockDim.x + threadIdx.x) >> 5;
    int lane = threadIdx.x & 31;
    if (node >= N_NODES) return;

    float di = g_dinv[node];
    float2 h = H2[node * 32 + lane];
    float ax = di * di * h.x, ay = di * di * h.y;

    int deg = g_fill[node];
    if (deg > MAXD) deg = MAXD;
    const int* sl = &g_slot[node * MAXD];
    int j = 0;
    for (; j + 4 <= deg; j += 4) {
        int s0 = sl[j], s1 = sl[j + 1], s2 = sl[j + 2], s3 = sl[j + 3];
        float w0 = di * g_dinv[s0], w1 = di * g_dinv[s1];
        float w2 = di * g_dinv[s2], w3 = di * g_dinv[s3];
        float2 v0 = H2[s0 * 32 + lane];
        float2 v1 = H2[s1 * 32 + lane];
        float2 v2 = H2[s2 * 32 + lane];
        float2 v3 = H2[s3 * 32 + lane];
        ax += w0 * v0.x + w1 * v1.x + w2 * v2.x + w3 * v3.x;
        ay += w0 * v0.y + w1 * v1.y + w2 * v2.y + w3 * v3.y;
    }
    for (; j < deg; j++) {
        int s = sl[j];
        float w = di * g_dinv[s];
        float2 v = H2[s * 32 + lane];
        ax += w * v.x; ay += w * v.y;
    }

    float2 bb = ((const float2*)bias)[lane];
    ax += bb.x; ay += bb.y;
    if (RELU) { ax = fmaxf(ax, 0.f); ay = fmaxf(ay, 0.f); }
    float2 o = {ax, ay};
    O2[node * 32 + lane] = o;
}

template <bool RELU, int HSEL>
__global__ void agg32_kernel(const float* __restrict__ bias,
                             float* __restrict__ Oarg, int out_sel) {
    const float* H = buf_sel(HSEL);
    float* O = (out_sel < 0) ? Oarg : buf_sel(out_sel);

    int node = (blockIdx.x * blockDim.x + threadIdx.x) >> 5;
    int lane = threadIdx.x & 31;
    if (node >= N_NODES) return;

    float di = g_dinv[node];
    float acc = di * di * H[node * 32 + lane];

    int deg = g_fill[node];
    if (deg > MAXD) deg = MAXD;
    const int* sl = &g_slot[node * MAXD];
    int j = 0;
    for (; j + 4 <= deg; j += 4) {
        int s0 = sl[j], s1 = sl[j + 1], s2 = sl[j + 2], s3 = sl[j + 3];
        float w0 = di * g_dinv[s0], w1 = di * g_dinv[s1];
        float w2 = di * g_dinv[s2], w3 = di * g_dinv[s3];
        acc += w0 * H[s0 * 32 + lane] + w1 * H[s1 * 32 + lane]
             + w2 * H[s2 * 32 + lane] + w3 * H[s3 * 32 + lane];
    }
    for (; j < deg; j++) {
        int s = sl[j];
        acc += di * g_dinv[s] * H[s * 32 + lane];
    }

    float v = acc + bias[lane];
    if (RELU) v = fmaxf(v, 0.f);
    O[node * 32 + lane] = v;
}

// ---------------------------------------------------------------- launch
extern "C" void kernel_launch(void* const* d_in, const int* in_sizes, int n_in,
                              void* d_out, int out_size) {
    const float* x  = (const float*)d_in[0];
    const int*   ei = (const int*)d_in[1];
    const float* W1 = (const float*)d_in[2];
    const float* b1 = (const float*)d_in[3];
    const float* W2 = (const float*)d_in[4];
    const float* b2 = (const float*)d_in[5];
    float*       out = (float*)d_out;

    static cudaStream_t s_side = nullptr;
    static cudaEvent_t  s_fork = nullptr, s_join = nullptr;
    static bool attr_done = false;
    if (!attr_done) {
        cudaFuncSetAttribute(gemm1_pipe_kernel,
                             cudaFuncAttributeMaxDynamicSharedMemorySize,
                             G1_SMEM);
        attr_done = true;
    }
    if (!s_side) {
        if (cudaStreamCreateWithFlags(&s_side, cudaStreamNonBlocking) != cudaSuccess)
            s_side = nullptr;
        cudaEventCreateWithFlags(&s_fork, cudaEventDisableTiming);
        cudaEventCreateWithFlags(&s_join, cudaEventDisableTiming);
    }
    cudaStream_t sc = s_side ? s_side : 0;

    // fork: adjacency build on side stream
    if (s_side) {
        cudaEventRecord(s_fork, 0);
        cudaStreamWaitEvent(sc, s_fork, 0);
    }
    zero_fill_kernel<<<(N_NODES / 4 + 255) / 256, 256, 0, sc>>>();
    scatter_kernel<<<(N_EDGES / 2 + 255) / 256, 256, 0, sc>>>(ei);
    dinv_kernel<<<(N_NODES + 255) / 256, 256, 0, sc>>>();
    if (s_side) cudaEventRecord(s_join, sc);

    // concurrently on main stream: GEMM1 (padded-stride pipelined tf32 wmma)
    gemm1_pipe_kernel<<<G1_GRID, 256, G1_SMEM>>>(x, W1);

    // join: agg needs adjacency + g_h1
    if (s_side) cudaStreamWaitEvent(0, s_join, 0);

    agg64_kernel<true, 0><<<(N_NODES * 32 + 255) / 256, 256>>>(b1, nullptr, 1);

    gemm_kernel<HID_DIM, OUT_DIM, 4, 16, 1>
        <<<(N_NODES + 511) / 512, 256>>>(nullptr, W2, 2);
    agg32_kernel<false, 2><<<(N_NODES * 32 + 255) / 256, 256>>>(b2, out, -1);
}

// round 17
// speedup vs baseline: 1.2223x; 1.0334x over previous
#include <cuda_runtime.h>
#include <cuda_fp16.h>
#include <mma.h>
#include <cstdint>

using namespace nvcuda;

#define N_NODES 100000
#define N_EDGES 1600000
#define IN_DIM  128
#define HID_DIM 64
#define OUT_DIM 32
#define MAXD    64        // P(Poisson(16) > 64) ~ 1e-18: safe padded degree

#define G1_GRID  296      // 2 CTAs/SM x 148 SMs
#define G1_TILES ((N_NODES + 63) / 64)   // 1563
#define XLD 132           // padded X tile leading dim (floats)
#define WLD 68            // padded W leading dim (floats)
#define SLD 68            // epilogue scratch leading dim (16B multiple)

// ---- device scratch (static globals: no runtime allocation allowed) ----
__device__ int   g_fill[N_NODES];
__device__ int   g_slot[N_NODES * MAXD];
__device__ float g_dinv[N_NODES];
__device__ __align__(16) __half g_h1h[N_NODES * HID_DIM];   // fp16 x@W1
__device__ float g_a1[N_NODES * HID_DIM];                   // fp32 relu(agg+b1)
__device__ __align__(16) __half g_h2h[N_NODES * OUT_DIM];   // fp16 a1@W2

// ---- f32x2 packed helpers ----
__device__ __forceinline__ unsigned long long ffma2(
    unsigned long long a, unsigned long long b, unsigned long long c) {
    unsigned long long d;
    asm("fma.rn.f32x2 %0, %1, %2, %3;" : "=l"(d) : "l"(a), "l"(b), "l"(c));
    return d;
}
__device__ __forceinline__ unsigned long long pack2(float x) {
    unsigned long long d;
    asm("mov.b64 %0, {%1, %1};" : "=l"(d) : "f"(x));
    return d;
}
__device__ __forceinline__ void lds128_u64x2(
    unsigned long long& a, unsigned long long& b, uint32_t saddr) {
    asm volatile("ld.shared.v2.u64 {%0, %1}, [%2];"
                 : "=l"(a), "=l"(b) : "r"(saddr));
}
__device__ __forceinline__ void cp16(uint32_t saddr, const void* gaddr) {
    asm volatile("cp.async.ca.shared.global [%0], [%1], 16;"
                 :: "r"(saddr), "l"(gaddr));
}

// ---------------------------------------------------------------- CSR build
__global__ void zero_fill_kernel() {
    int i = blockIdx.x * blockDim.x + threadIdx.x;
    if (i * 4 < N_NODES) {
        int4 z = {0, 0, 0, 0};
        if (i * 4 + 3 < N_NODES) *(int4*)&g_fill[i * 4] = z;
        else for (int k = i * 4; k < N_NODES; k++) g_fill[k] = 0;
    }
}

__global__ void scatter_kernel(const int* __restrict__ ei) {
    int t = blockIdx.x * blockDim.x + threadIdx.x;
    int e = t * 2;
    if (e + 2 <= N_EDGES) {
        int2 s2 = *(const int2*)&ei[e];
        int2 d2 = *(const int2*)&ei[N_EDGES + e];
        if ((unsigned)s2.x < N_NODES && (unsigned)d2.x < N_NODES) {
            int p = atomicAdd(&g_fill[d2.x], 1);
            if (p < MAXD) g_slot[d2.x * MAXD + p] = s2.x;
        }
        if ((unsigned)s2.y < N_NODES && (unsigned)d2.y < N_NODES) {
            int p = atomicAdd(&g_fill[d2.y], 1);
            if (p < MAXD) g_slot[d2.y * MAXD + p] = s2.y;
        }
    } else if (e < N_EDGES) {
        unsigned src = (unsigned)ei[e];
        unsigned dst = (unsigned)ei[N_EDGES + e];
        if (src < N_NODES && dst < N_NODES) {
            int p = atomicAdd(&g_fill[dst], 1);
            if (p < MAXD) g_slot[dst * MAXD + p] = (int)src;
        }
    }
}

__global__ void dinv_kernel() {
    int i = blockIdx.x * blockDim.x + threadIdx.x;
    if (i < N_NODES) g_dinv[i] = rsqrtf((float)(g_fill[i] + 1));
}

// ---------------------------------------------------------------- GEMM1: pipelined tf32 wmma -> fp16
__global__ __launch_bounds__(256, 2)
void gemm1_pipe_kernel(const float* __restrict__ X,
                       const float* __restrict__ W) {
    extern __shared__ float dsm[];
    float* Ws  = dsm;                       // 128*WLD floats
    float* Xs0 = dsm + 128 * WLD;           // 64*XLD floats
    float* Xs1 = Xs0 + 64 * XLD;

    const int tid  = threadIdx.x;
    const int warp = tid >> 5;
    const int rt = warp >> 2;           // 0..1
    const int ct = warp & 3;            // 0..3

    // stage W once, pre-rounded to tf32 (padded stride WLD)
    {
        const float4* W4 = (const float4*)W;
        for (int i = tid; i < IN_DIM * (HID_DIM / 4); i += 256) {
            int r  = i >> 4;
            int c4 = i & 15;
            float4 w = W4[r * 16 + c4];
            w.x = wmma::__float_to_tf32(w.x);
            w.y = wmma::__float_to_tf32(w.y);
            w.z = wmma::__float_to_tf32(w.z);
            w.w = wmma::__float_to_tf32(w.w);
            *(float4*)&Ws[r * WLD + c4 * 4] = w;
        }
    }

    const float4* X4 = (const float4*)X;
    const uint32_t xs_addr[2] = {
        (uint32_t)__cvta_generic_to_shared(Xs0),
        (uint32_t)__cvta_generic_to_shared(Xs1)
    };
    float* const xs_ptr[2] = {Xs0, Xs1};

    auto stage = [&](int b, int t) {
        int row0 = t * 64;
        uint32_t sb = xs_addr[b];
#pragma unroll
        for (int k = 0; k < 8; k++) {
            int l = tid + k * 256;
            int r = l >> 5, c4 = l & 31;
            int row = row0 + r;
            if (row >= N_NODES) row = N_NODES - 1;
            cp16(sb + (uint32_t)(r * XLD + c4 * 4) * 4, &X4[row * 32 + c4]);
        }
        asm volatile("cp.async.commit_group;");
    };

    int t0 = blockIdx.x;
    if (t0 < G1_TILES) stage(0, t0);
    __syncthreads();

    int cur = 0;
    for (int t = t0; t < G1_TILES; t += G1_GRID) {
        int tn = t + G1_GRID;
        bool has_next = (tn < G1_TILES);
        if (has_next) stage(1 - cur, tn);

        if (has_next) asm volatile("cp.async.wait_group 1;");
        else          asm volatile("cp.async.wait_group 0;");
        __syncthreads();

        float* Xt = xs_ptr[cur];
        wmma::fragment<wmma::accumulator, 16, 16, 8, float> acc0, acc1;
        wmma::fill_fragment(acc0, 0.0f);
        wmma::fill_fragment(acc1, 0.0f);

#pragma unroll
        for (int kt = 0; kt < 16; kt++) {
            wmma::fragment<wmma::matrix_a, 16, 16, 8, wmma::precision::tf32,
                           wmma::row_major> fa0, fa1;
            wmma::fragment<wmma::matrix_b, 16, 16, 8, wmma::precision::tf32,
                           wmma::row_major> fb;
            wmma::load_matrix_sync(fa0, &Xt[(rt * 16) * XLD + kt * 8], XLD);
            wmma::load_matrix_sync(fa1, &Xt[((rt + 2) * 16) * XLD + kt * 8], XLD);
            wmma::load_matrix_sync(fb, &Ws[(kt * 8) * WLD + ct * 16], WLD);
#pragma unroll
            for (int i = 0; i < fa0.num_elements; i++) {
                fa0.x[i] = wmma::__float_to_tf32(fa0.x[i]);
                fa1.x[i] = wmma::__float_to_tf32(fa1.x[i]);
            }
            wmma::mma_sync(acc0, fa0, fb, acc0);
            wmma::mma_sync(acc1, fa1, fb, acc1);
        }

        // epilogue: park acc in the (now free) cur X buffer, convert to fp16
        __syncthreads();   // all warps done with LDSM from Xt
        wmma::store_matrix_sync(&Xt[(rt * 16) * SLD + ct * 16], acc0, SLD,
                                wmma::mem_row_major);
        wmma::store_matrix_sync(&Xt[((rt + 2) * 16) * SLD + ct * 16], acc1, SLD,
                                wmma::mem_row_major);
        __syncthreads();

        int row0 = t * 64;
        __half2* H2 = (__half2*)g_h1h;
#pragma unroll
        for (int k = 0; k < 8; k++) {
            int i = tid + k * 256;          // 0..2047
            int r = i >> 5, c2 = i & 31;
            int row = row0 + r;
            if (row < N_NODES) {
                float2 f = *(float2*)&Xt[r * SLD + c2 * 2];
                H2[row * 32 + c2] = __float22half2_rn(f);
            }
        }

        __syncthreads();   // writes done before restaging into Xt's buffer
        cur ^= 1;
    }
}

#define G1_SMEM ((128 * WLD + 2 * 64 * XLD) * 4)   // 102400 B

// ---------------------------------------------------------------- GEMM2 (f32x2, fp32 in -> fp16 out)
// H2h[N,32] = a1[N,64] @ W2[64,32]
__launch_bounds__(256, 2)
__global__ void gemm2_kernel(const float* __restrict__ W) {
    constexpr int FIN = HID_DIM, FOUT = OUT_DIM;
    constexpr int CPT = 16, TR = 4;
    constexpr int CG = FOUT / CPT;   // 2
    constexpr int RG = 256 / CG;     // 128
    constexpr int RB = RG * TR;      // 512
    constexpr int C2 = CPT / 2;      // 8
    constexpr int C4 = CPT / 4;      // 4

    const float* X = g_a1;

    __shared__ float Ws[FIN * FOUT];
    for (int i = threadIdx.x; i < FIN * FOUT; i += 256) Ws[i] = W[i];
    __syncthreads();

    const int cg   = threadIdx.x % CG;
    const int rg   = threadIdx.x / CG;
    const int row0 = blockIdx.x * RB + rg * TR;

    const uint32_t ws_col = (uint32_t)__cvta_generic_to_shared(Ws)
                          + (uint32_t)(cg * CPT * 4);

    unsigned long long acc[TR][C2];
#pragma unroll
    for (int r = 0; r < TR; r++)
#pragma unroll
        for (int c = 0; c < C2; c++) acc[r][c] = 0ull;

    const float4* X4 = (const float4*)X;
    int rowc[TR];
#pragma unroll
    for (int r = 0; r < TR; r++) {
        int row = row0 + r;
        rowc[r] = (row < N_NODES) ? row : (N_NODES - 1);
    }

#pragma unroll 4
    for (int kk = 0; kk < FIN / 4; kk++) {
        float4 xv[TR];
#pragma unroll
        for (int r = 0; r < TR; r++)
            xv[r] = X4[rowc[r] * (FIN / 4) + kk];
#pragma unroll
        for (int k4 = 0; k4 < 4; k4++) {
            unsigned long long wv[C2];
            uint32_t kaddr = ws_col + (uint32_t)((kk * 4 + k4) * FOUT * 4);
#pragma unroll
            for (int c = 0; c < C4; c++)
                lds128_u64x2(wv[c * 2], wv[c * 2 + 1], kaddr + c * 16);
#pragma unroll
            for (int r = 0; r < TR; r++) {
                float xk = (k4 == 0) ? xv[r].x : (k4 == 1) ? xv[r].y
                         : (k4 == 2) ? xv[r].z : xv[r].w;
                unsigned long long xx = pack2(xk);
#pragma unroll
                for (int c = 0; c < C2; c++)
                    acc[r][c] = ffma2(xx, wv[c], acc[r][c]);
            }
        }
    }

#pragma unroll
    for (int r = 0; r < TR; r++) {
        int row = row0 + r;
        if (row < N_NODES) {
            __half2 hv[C2];
#pragma unroll
            for (int c = 0; c < C2; c++) {
                float2 f = *(float2*)&acc[r][c];
                hv[c] = __float22half2_rn(f);
            }
            uint4* dst = (uint4*)&g_h2h[row * FOUT + cg * CPT];
            dst[0] = ((uint4*)hv)[0];
            dst[1] = ((uint4*)hv)[1];
        }
    }
}

// ---------------------------------------------------------------- aggregate
// warp per node; fp16 gathered rows, fp32 accumulation.
__global__ void agg64_kernel(const float* __restrict__ bias) {
    const __half2* H2 = (const __half2*)g_h1h;
    float2* O2 = (float2*)g_a1;

    int node = (blockIdx.x * blockDim.x + threadIdx.x) >> 5;
    int lane = threadIdx.x & 31;
    if (node >= N_NODES) return;

    float di = g_dinv[node];
    float2 h = __half22float2(H2[node * 32 + lane]);
    float ax = di * di * h.x, ay = di * di * h.y;

    int deg = g_fill[node];
    if (deg > MAXD) deg = MAXD;
    const int* sl = &g_slot[node * MAXD];
    int j = 0;
    for (; j + 4 <= deg; j += 4) {
        int s0 = sl[j], s1 = sl[j + 1], s2 = sl[j + 2], s3 = sl[j + 3];
        float w0 = di * g_dinv[s0], w1 = di * g_dinv[s1];
        float w2 = di * g_dinv[s2], w3 = di * g_dinv[s3];
        float2 v0 = __half22float2(H2[s0 * 32 + lane]);
        float2 v1 = __half22float2(H2[s1 * 32 + lane]);
        float2 v2 = __half22float2(H2[s2 * 32 + lane]);
        float2 v3 = __half22float2(H2[s3 * 32 + lane]);
        ax += w0 * v0.x + w1 * v1.x + w2 * v2.x + w3 * v3.x;
        ay += w0 * v0.y + w1 * v1.y + w2 * v2.y + w3 * v3.y;
    }
    for (; j < deg; j++) {
        int s = sl[j];
        float w = di * g_dinv[s];
        float2 v = __half22float2(H2[s * 32 + lane]);
        ax += w * v.x; ay += w * v.y;
    }

    float2 bb = ((const float2*)bias)[lane];
    ax += bb.x; ay += bb.y;
    ax = fmaxf(ax, 0.f); ay = fmaxf(ay, 0.f);
    float2 o = {ax, ay};
    O2[node * 32 + lane] = o;
}

__global__ void agg32_kernel(const float* __restrict__ bias,
                             float* __restrict__ O) {
    int node = (blockIdx.x * blockDim.x + threadIdx.x) >> 5;
    int lane = threadIdx.x & 31;
    if (node >= N_NODES) return;

    float di = g_dinv[node];
    float acc = di * di * __half2float(g_h2h[node * 32 + lane]);

    int deg = g_fill[node];
    if (deg > MAXD) deg = MAXD;
    const int* sl = &g_slot[node * MAXD];
    int j = 0;
    for (; j + 4 <= deg; j += 4) {
        int s0 = sl[j], s1 = sl[j + 1], s2 = sl[j + 2], s3 = sl[j + 3];
        float w0 = di * g_dinv[s0], w1 = di * g_dinv[s1];
        float w2 = di * g_dinv[s2], w3 = di * g_dinv[s3];
        acc += w0 * __half2float(g_h2h[s0 * 32 + lane])
             + w1 * __half2float(g_h2h[s1 * 32 + lane])
             + w2 * __half2float(g_h2h[s2 * 32 + lane])
             + w3 * __half2float(g_h2h[s3 * 32 + lane]);
    }
    for (; j < deg; j++) {
        int s = sl[j];
        acc += di * g_dinv[s] * __half2float(g_h2h[s * 32 + lane]);
    }

    O[node * 32 + lane] = acc + bias[lane];
}

// ---------------------------------------------------------------- launch
extern "C" void kernel_launch(void* const* d_in, const int* in_sizes, int n_in,
                              void* d_out, int out_size) {
    const float* x  = (const float*)d_in[0];
    const int*   ei = (const int*)d_in[1];
    const float* W1 = (const float*)d_in[2];
    const float* b1 = (const float*)d_in[3];
    const float* W2 = (const float*)d_in[4];
    const float* b2 = (const float*)d_in[5];
    float*       out = (float*)d_out;

    static cudaStream_t s_side = nullptr;
    static cudaEvent_t  s_fork = nullptr, s_join = nullptr;
    static bool attr_done = false;
    if (!attr_done) {
        cudaFuncSetAttribute(gemm1_pipe_kernel,
                             cudaFuncAttributeMaxDynamicSharedMemorySize,
                             G1_SMEM);
        attr_done = true;
    }
    if (!s_side) {
        if (cudaStreamCreateWithFlags(&s_side, cudaStreamNonBlocking) != cudaSuccess)
            s_side = nullptr;
        cudaEventCreateWithFlags(&s_fork, cudaEventDisableTiming);
        cudaEventCreateWithFlags(&s_join, cudaEventDisableTiming);
    }
    cudaStream_t sc = s_side ? s_side : 0;

    // fork: adjacency build on side stream
    if (s_side) {
        cudaEventRecord(s_fork, 0);
        cudaStreamWaitEvent(sc, s_fork, 0);
    }
    zero_fill_kernel<<<(N_NODES / 4 + 255) / 256, 256, 0, sc>>>();
    scatter_kernel<<<(N_EDGES / 2 + 255) / 256, 256, 0, sc>>>(ei);
    dinv_kernel<<<(N_NODES + 255) / 256, 256, 0, sc>>>();
    if (s_side) cudaEventRecord(s_join, sc);

    // concurrently: GEMM1 (tf32 wmma, fp16 output)
    gemm1_pipe_kernel<<<G1_GRID, 256, G1_SMEM>>>(x, W1);

    // join: agg needs adjacency + h1
    if (s_side) cudaStreamWaitEvent(0, s_join, 0);

    agg64_kernel<<<(N_NODES * 32 + 255) / 256, 256>>>(b1);
    gemm2_kernel<<<(N_NODES + 511) / 512, 256>>>(W2);
    agg32_kernel<<<(N_NODES * 32 + 255) / 256, 256>>>(b2, out);
}